// round 7
// baseline (speedup 1.0000x reference)
#include <cuda_runtime.h>
#include <math.h>

#define DD 2048
#define LL 128
#define BB 64
#define NTHR 256
#define WPB (NTHR / 32)     // 8 warps per block
#define BPSM 4              // co-resident blocks per SM

// Scratch (no device allocation allowed)
__device__ float    g_dj[BB * LL];
__device__ float    g_ek[BB * LL];
__device__ float    g_psum[BB];
__device__ int      g_pcnt[BB];
__device__ unsigned g_bar;    // monotonic grid-barrier counter (graph-replay safe)
__device__ unsigned g_done;   // monotonic phase-2 completion counter

__device__ __forceinline__ float softplus_stable(float x) {
    return fmaxf(x, 0.f) + log1pf(expf(-fabsf(x)));
}

__global__ __launch_bounds__(NTHR, BPSM) void dli_fused_kernel(
    const float* __restrict__ enc,   // [64,128,2048]
    const int*   __restrict__ mask,  // [64,128]
    const float* __restrict__ W,     // [4096,2] row-major
    const float* __restrict__ bias,  // [2]
    float* __restrict__ out)
{
    __shared__ float s_wl[DD];
    __shared__ float s_wr[DD];
    __shared__ float s_red[NTHR];
    __shared__ float s_dj[LL];
    __shared__ float s_ek[LL];
    __shared__ int   s_len;

    const int tid  = threadIdx.x;
    const int nblk = gridDim.x;

    // ---- Phase 0: column-diff weight vectors in smem (per block) ----------
    for (int d = tid; d < DD; d += NTHR) {
        float2 a = *(const float2*)(W + 2 * d);
        float2 r = *(const float2*)(W + 2 * (DD + d));
        s_wl[d] = a.y - a.x;
        s_wr[d] = r.y - r.x;
    }
    __syncthreads();

    // ---- Phase 1: warp-per-row dual dot products (67 MB HBM stream) -------
    // 4 blocks/SM x 8 warps = 32 warps/SM: latency hidden by warp count.
    const int warp = tid >> 5;
    const int lane = tid & 31;
    const float4* wl4 = (const float4*)s_wl;
    const float4* wr4 = (const float4*)s_wr;

    for (int row = blockIdx.x * WPB + warp; row < BB * LL; row += nblk * WPB) {
        const float4* e4 = (const float4*)(enc + (size_t)row * DD);
        float sd = 0.f, se = 0.f;
#pragma unroll
        for (int it = 0; it < DD / 4 / 32; ++it) {   // 16 chunks
            int i = lane + it * 32;
            float4 e = e4[i];
            float4 a = wl4[i];
            float4 r = wr4[i];
            sd = fmaf(e.x, a.x, sd); sd = fmaf(e.y, a.y, sd);
            sd = fmaf(e.z, a.z, sd); sd = fmaf(e.w, a.w, sd);
            se = fmaf(e.x, r.x, se); se = fmaf(e.y, r.y, se);
            se = fmaf(e.z, r.z, se); se = fmaf(e.w, r.w, se);
        }
#pragma unroll
        for (int o = 16; o; o >>= 1) {
            sd += __shfl_down_sync(0xFFFFFFFFu, sd, o);
            se += __shfl_down_sync(0xFFFFFFFFu, se, o);
        }
        if (lane == 0) {
            g_dj[row] = sd;
            g_ek[row] = se;
        }
    }

    // ---- Grid barrier (monotonic counter: no reset race across replays) ---
    __syncthreads();
    if (tid == 0) {
        __threadfence();
        unsigned old    = atomicAdd(&g_bar, 1u);
        unsigned target = (old / (unsigned)nblk + 1u) * (unsigned)nblk;
        while (*(volatile unsigned*)&g_bar < target) { }
        __threadfence();
    }
    __syncthreads();

    // ---- Phase 2: blocks 0..63 — pair softplus sweep per batch ------------
    if (blockIdx.x >= BB) return;
    const int b = blockIdx.x;

    // turn length = sum(mask[b,:])
    float m = (tid < LL) ? (float)mask[b * LL + tid] : 0.f;
    s_red[tid] = m;
    __syncthreads();
#pragma unroll
    for (int o = NTHR / 2; o; o >>= 1) {
        if (tid < o) s_red[tid] += s_red[tid + o];
        __syncthreads();
    }
    if (tid == 0) s_len = (int)(s_red[0] + 0.5f);

    if (tid < LL) {
        s_dj[tid] = __ldcg(&g_dj[b * LL + tid]);   // bypass L1: cross-SM data
        s_ek[tid] = __ldcg(&g_ek[b * LL + tid]);
    }
    __syncthreads();

    const int   len = s_len;
    const float db  = bias[1] - bias[0];
    float acc = 0.f;
    for (int j = 1; j < len; ++j) {
        float dj = s_dj[j];
        for (int k = tid; k < j; k += NTHR) {
            float x = dj + s_ek[k] + db;
            if (k == j - 1) x = -x;         // label 1 -> softplus(-(z1-z0))
            acc += softplus_stable(x);
        }
    }

    s_red[tid] = acc;
    __syncthreads();
#pragma unroll
    for (int o = NTHR / 2; o; o >>= 1) {
        if (tid < o) s_red[tid] += s_red[tid + o];
        __syncthreads();
    }

    // Deterministic per-batch partials; last finishing block finalizes.
    if (tid == 0) {
        __stcg(&g_psum[b], s_red[0]);
        __stcg(&g_pcnt[b], len * (len - 1) / 2);
        __threadfence();
        unsigned old = atomicAdd(&g_done, 1u);
        if ((old % (unsigned)BB) == (unsigned)(BB - 1)) {
            __threadfence();
            double s = 0.0;
            int    c = 0;
            for (int i = 0; i < BB; ++i) {
                s += (double)__ldcg(&g_psum[i]);
                c += __ldcg(&g_pcnt[i]);
            }
            if (c < 1) c = 1;
            out[0] = (float)(s / (double)c);
        }
    }
}

extern "C" void kernel_launch(void* const* d_in, const int* in_sizes, int n_in,
                              void* d_out, int out_size) {
    const float* enc  = (const float*)d_in[0];  // [64,128,2048] f32
    const int*   mask = (const int*)d_in[1];    // [64,128] i32
    const float* W    = (const float*)d_in[2];  // [4096,2] f32
    const float* bias = (const float*)d_in[3];  // [2] f32
    float* out = (float*)d_out;

    int sm = 148;
    cudaDeviceGetAttribute(&sm, cudaDevAttrMultiProcessorCount, 0);
    if (sm > 1024) sm = 1024;           // paranoia bound
    if (sm < BB)   sm = BB;             // phase 2 needs >= 64 blocks

    dli_fused_kernel<<<sm * BPSM, NTHR>>>(enc, mask, W, bias, out);
}

// round 8
// speedup vs baseline: 1.7259x; 1.7259x over previous
#include <cuda_runtime.h>
#include <math.h>

#define DD 2048
#define LL 128
#define BB 64
#define NTHR 256
#define BPSM 2
#define CHUNKS 16   // 2048 / 4 / 32 float4-chunks per lane per row

// Scratch (no device allocation allowed)
__device__ float    g_dj[BB * LL];
__device__ float    g_ek[BB * LL];
__device__ float    g_psum[BB];
__device__ int      g_pcnt[BB];
__device__ unsigned g_bar;    // monotonic grid-barrier counter (graph-replay safe)
__device__ unsigned g_done;   // monotonic phase-2 completion counter

__device__ __forceinline__ float softplus_stable(float x) {
    return fmaxf(x, 0.f) + log1pf(expf(-fabsf(x)));
}

__global__ __launch_bounds__(NTHR, BPSM) void dli_fused_kernel(
    const float* __restrict__ enc,   // [64,128,2048]
    const int*   __restrict__ mask,  // [64,128]
    const float* __restrict__ W,     // [4096,2] row-major
    const float* __restrict__ bias,  // [2]
    float* __restrict__ out)
{
    __shared__ float s_wl[DD];
    __shared__ float s_wr[DD];
    __shared__ float s_red[NTHR];
    __shared__ float s_dj[LL];
    __shared__ float s_ek[LL];
    __shared__ int   s_len;

    const int tid  = threadIdx.x;
    const int nblk = gridDim.x;

    // ---- Phase 0: column-diff weight vectors in smem (per block) ----------
    for (int d = tid; d < DD; d += NTHR) {
        float2 a = *(const float2*)(W + 2 * d);
        float2 r = *(const float2*)(W + 2 * (DD + d));
        s_wl[d] = a.y - a.x;
        s_wr[d] = r.y - r.x;
    }
    __syncthreads();

    // ---- Phase 1: warp-per-row dual dot products (67 MB HBM stream) -------
    // Stage all 16 float4 loads into registers FIRST, then consume against
    // smem weights. 2 blocks/SM -> 16 warps/SM of this pattern.
    const int warp = tid >> 5;
    const int lane = tid & 31;
    const float4* wl4 = (const float4*)s_wl;
    const float4* wr4 = (const float4*)s_wr;
    const int warps_per_blk = NTHR / 32;

    for (int row = blockIdx.x * warps_per_blk + warp; row < BB * LL;
         row += nblk * warps_per_blk) {
        const float4* e4 = (const float4*)(enc + (size_t)row * DD);

        float4 e[CHUNKS];
#pragma unroll
        for (int it = 0; it < CHUNKS; ++it)
            e[it] = __ldcs(&e4[lane + it * 32]);   // streaming: read-once data

        float sd = 0.f, se = 0.f;
#pragma unroll
        for (int it = 0; it < CHUNKS; ++it) {
            int i = lane + it * 32;
            float4 a = wl4[i];
            float4 r = wr4[i];
            sd += e[it].x * a.x + e[it].y * a.y + e[it].z * a.z + e[it].w * a.w;
            se += e[it].x * r.x + e[it].y * r.y + e[it].z * r.z + e[it].w * r.w;
        }
#pragma unroll
        for (int o = 16; o; o >>= 1) {
            sd += __shfl_down_sync(0xFFFFFFFFu, sd, o);
            se += __shfl_down_sync(0xFFFFFFFFu, se, o);
        }
        if (lane == 0) {
            g_dj[row] = sd;
            g_ek[row] = se;
        }
    }

    // ---- Grid barrier (monotonic counter: no reset race across replays) ---
    __syncthreads();
    if (tid == 0) {
        __threadfence();
        unsigned old    = atomicAdd(&g_bar, 1u);
        unsigned target = (old / (unsigned)nblk + 1u) * (unsigned)nblk;
        while (*(volatile unsigned*)&g_bar < target) { }
        __threadfence();
    }
    __syncthreads();

    // ---- Phase 2: blocks 0..63 — pair softplus sweep per batch ------------
    if (blockIdx.x >= BB) return;
    const int b = blockIdx.x;

    // turn length = sum(mask[b,:])
    float m = (tid < LL) ? (float)mask[b * LL + tid] : 0.f;
    s_red[tid] = m;
    __syncthreads();
#pragma unroll
    for (int o = NTHR / 2; o; o >>= 1) {
        if (tid < o) s_red[tid] += s_red[tid + o];
        __syncthreads();
    }
    if (tid == 0) s_len = (int)(s_red[0] + 0.5f);

    if (tid < LL) {
        s_dj[tid] = __ldcg(&g_dj[b * LL + tid]);   // bypass L1: cross-SM data
        s_ek[tid] = __ldcg(&g_ek[b * LL + tid]);
    }
    __syncthreads();

    const int   len = s_len;
    const float db  = bias[1] - bias[0];
    float acc = 0.f;
    for (int j = 1; j < len; ++j) {
        float dj = s_dj[j];
        for (int k = tid; k < j; k += NTHR) {
            float x = dj + s_ek[k] + db;
            if (k == j - 1) x = -x;         // label 1 -> softplus(-(z1-z0))
            acc += softplus_stable(x);
        }
    }

    s_red[tid] = acc;
    __syncthreads();
#pragma unroll
    for (int o = NTHR / 2; o; o >>= 1) {
        if (tid < o) s_red[tid] += s_red[tid + o];
        __syncthreads();
    }

    // Deterministic per-batch partials; last finishing block finalizes.
    if (tid == 0) {
        __stcg(&g_psum[b], s_red[0]);
        __stcg(&g_pcnt[b], len * (len - 1) / 2);
        __threadfence();
        unsigned old = atomicAdd(&g_done, 1u);
        if ((old % (unsigned)BB) == (unsigned)(BB - 1)) {
            __threadfence();
            double s = 0.0;
            int    c = 0;
            for (int i = 0; i < BB; ++i) {
                s += (double)__ldcg(&g_psum[i]);
                c += __ldcg(&g_pcnt[i]);
            }
            if (c < 1) c = 1;
            out[0] = (float)(s / (double)c);
        }
    }
}

extern "C" void kernel_launch(void* const* d_in, const int* in_sizes, int n_in,
                              void* d_out, int out_size) {
    const float* enc  = (const float*)d_in[0];  // [64,128,2048] f32
    const int*   mask = (const int*)d_in[1];    // [64,128] i32
    const float* W    = (const float*)d_in[2];  // [4096,2] f32
    const float* bias = (const float*)d_in[3];  // [2] f32
    float* out = (float*)d_out;

    int sm = 148;
    cudaDeviceGetAttribute(&sm, cudaDevAttrMultiProcessorCount, 0);
    if (sm > 1024) sm = 1024;           // paranoia bound
    if (sm < BB)   sm = BB;             // phase 2 needs >= 64 blocks

    dli_fused_kernel<<<sm * BPSM, NTHR>>>(enc, mask, W, bias, out);
}